// round 1
// baseline (speedup 1.0000x reference)
#include <cuda_runtime.h>

#define NMAX 100000
#define EMAX 3200000
#define GMAX 256
#define FULL 0xFFFFFFFFu

// ---- device scratch (static, no runtime allocation) ----
__device__ int   g_cnt_row[NMAX];
__device__ int   g_cnt_col[NMAX];
__device__ int   g_start[NMAX];
__device__ int   g_cursor[NMAX];
__device__ int   g_gcursor;
__device__ float g_dis[NMAX];
__device__ int   g_src[EMAX];
__device__ float g_norm[EMAX];
__device__ float g_h1[NMAX * 32];
__device__ float g_h2[NMAX * 64];
__device__ float g_pooled[GMAX * 64];

// ---------------------------------------------------------------------------
// K0: zero counters + pooled
__global__ void k_init(int n, int g64) {
    int i = blockIdx.x * blockDim.x + threadIdx.x;
    if (i < n) { g_cnt_row[i] = 0; g_cnt_col[i] = 0; g_cursor[i] = 0; }
    if (i < g64) g_pooled[i] = 0.0f;
    if (i == 0) g_gcursor = 0;
}

// K1: degree histograms (row for normalization, col for CSR buckets)
__global__ void k_hist(const int* __restrict__ ei, int e) {
    int i = blockIdx.x * blockDim.x + threadIdx.x;
    if (i >= e) return;
    atomicAdd(&g_cnt_row[ei[i]], 1);
    atomicAdd(&g_cnt_col[ei[e + i]], 1);
}

// K2: dis = rsqrt(deg_row + 1); private CSR ranges via warp-aggregated cursor
__global__ void k_alloc(int n) {
    int i = blockIdx.x * blockDim.x + threadIdx.x;
    int lane = threadIdx.x & 31;
    bool valid = (i < n);
    int c = valid ? g_cnt_col[i] : 0;
    int inc = c;
    #pragma unroll
    for (int o = 1; o < 32; o <<= 1) {
        int t = __shfl_up_sync(FULL, inc, o);
        if (lane >= o) inc += t;
    }
    int ex = inc - c;
    int tot = __shfl_sync(FULL, inc, 31);
    int base = 0;
    if (lane == 31) base = atomicAdd(&g_gcursor, tot);
    base = __shfl_sync(FULL, base, 31);
    if (valid) {
        g_start[i] = base + ex;
        g_dis[i] = rsqrtf((float)(g_cnt_row[i] + 1));  // +1 self loop; always > 0
    }
}

// K3: scatter edges into per-destination CSR slots; store precomputed norm
__global__ void k_fill(const int* __restrict__ ei, int e) {
    int i = blockIdx.x * blockDim.x + threadIdx.x;
    if (i >= e) return;
    int r = ei[i];
    int c = ei[e + i];
    int slot = g_start[c] + atomicAdd(&g_cursor[c], 1);
    g_src[slot] = r;
    g_norm[slot] = g_dis[r] * g_dis[c];
}

// K4: layer 1 — aggregate pos (3ch) per node, then 3->32 GEMV + ReLU
__global__ void k_layer1(const float* __restrict__ pos,
                         const float* __restrict__ W1,
                         const float* __restrict__ b1, int n) {
    __shared__ float sW1[96];
    __shared__ float sb1[32];
    int tid = threadIdx.x;
    if (tid < 96) sW1[tid] = W1[tid];
    if (tid < 32) sb1[tid] = b1[tid];
    __syncthreads();
    int w = tid >> 5, lane = tid & 31;
    int v = blockIdx.x * 8 + w;
    if (v >= n) return;
    int e0 = g_start[v];
    int e1 = e0 + g_cnt_col[v];
    float ax = 0.f, ay = 0.f, az = 0.f;
    for (int j = e0 + lane; j < e1; j += 32) {
        int s = g_src[j];
        float nm = g_norm[j];
        ax = fmaf(nm, pos[s * 3 + 0], ax);
        ay = fmaf(nm, pos[s * 3 + 1], ay);
        az = fmaf(nm, pos[s * 3 + 2], az);
    }
    #pragma unroll
    for (int o = 16; o; o >>= 1) {
        ax += __shfl_xor_sync(FULL, ax, o);
        ay += __shfl_xor_sync(FULL, ay, o);
        az += __shfl_xor_sync(FULL, az, o);
    }
    float dv = g_dis[v];
    float sn = dv * dv;  // self-loop norm
    ax = fmaf(sn, pos[v * 3 + 0], ax);
    ay = fmaf(sn, pos[v * 3 + 1], ay);
    az = fmaf(sn, pos[v * 3 + 2], az);
    float o = fmaf(sW1[lane * 3 + 0], ax,
             fmaf(sW1[lane * 3 + 1], ay,
             fmaf(sW1[lane * 3 + 2], az, sb1[lane])));
    g_h1[v * 32 + lane] = fmaxf(o, 0.f);
}

// K5: layer 2 — aggregate h1 (32ch, coalesced 128B gathers), 32->64 GEMV + ReLU
__global__ void k_layer2(const float* __restrict__ W2,
                         const float* __restrict__ b2, int n) {
    __shared__ float sW2T[2048];    // [k][c] transposed: conflict-free GEMV
    __shared__ float sb2[64];
    __shared__ float sacc[8][33];
    int tid = threadIdx.x;
    for (int idx = tid; idx < 2048; idx += 256) {
        int c = idx >> 5, k = idx & 31;
        sW2T[k * 64 + c] = W2[idx];   // W2 row-major [64][32]
    }
    if (tid < 64) sb2[tid] = b2[tid];
    __syncthreads();
    int w = tid >> 5, lane = tid & 31;
    int v = blockIdx.x * 8 + w;
    if (v >= n) return;
    int e0 = g_start[v];
    int e1 = e0 + g_cnt_col[v];
    float acc = 0.f;
    for (int base = e0; base < e1; base += 32) {
        int j = base + lane;
        int s = 0; float nm = 0.f;
        if (j < e1) { s = g_src[j]; nm = g_norm[j]; }
        int m = e1 - base; if (m > 32) m = 32;
        for (int t = 0; t < m; t++) {
            int   sv = __shfl_sync(FULL, s, t);
            float nv = __shfl_sync(FULL, nm, t);
            acc = fmaf(nv, g_h1[sv * 32 + lane], acc);   // 128B coalesced
        }
    }
    float dv = g_dis[v];
    acc = fmaf(dv * dv, g_h1[v * 32 + lane], acc);       // self loop
    sacc[w][lane] = acc;
    __syncwarp();
    float oa = sb2[lane], ob = sb2[lane + 32];
    #pragma unroll
    for (int k = 0; k < 32; k++) {
        float a = sacc[w][k];
        oa = fmaf(a, sW2T[k * 64 + lane], oa);
        ob = fmaf(a, sW2T[k * 64 + lane + 32], ob);
    }
    g_h2[v * 64 + lane]      = fmaxf(oa, 0.f);
    g_h2[v * 64 + lane + 32] = fmaxf(ob, 0.f);
}

// K6: segment max pooling (batch sorted => run-local max, few atomics)
__global__ void k_pool(const int* __restrict__ batch, int n) {
    int c = threadIdx.x;                 // channel 0..63
    int r = threadIdx.y;                 // 0..3
    int v0 = (blockIdx.x * 4 + r) * 128;
    if (v0 >= n) return;
    int v1 = v0 + 128; if (v1 > n) v1 = n;
    int g = batch[v0];
    float m = 0.f;                       // ReLU outputs >= 0
    for (int v = v0; v < v1; v++) {
        int gb = batch[v];
        if (gb != g) {
            atomicMax((int*)&g_pooled[g * 64 + c], __float_as_int(m));
            g = gb; m = 0.f;
        }
        m = fmaxf(m, g_h2[v * 64 + c]);
    }
    atomicMax((int*)&g_pooled[g * 64 + c], __float_as_int(m));
}

// K7: classifier head [G,64] @ Wc^T + bc -> [G,2]
__global__ void k_cls(const float* __restrict__ Wc,
                      const float* __restrict__ bc,
                      float* __restrict__ out, int G) {
    __shared__ float sWc[128];
    __shared__ float sbc[2];
    int t = threadIdx.x;
    if (t < 128) sWc[t] = Wc[t];
    if (t < 2) sbc[t] = bc[t];
    __syncthreads();
    if (t >= G * 2) return;
    int g = t >> 1, k = t & 1;
    float s = sbc[k];
    const float* p = &g_pooled[g * 64];
    #pragma unroll
    for (int c = 0; c < 64; c++)
        s = fmaf(p[c], sWc[k * 64 + c], s);
    out[t] = s;
}

// ---------------------------------------------------------------------------
extern "C" void kernel_launch(void* const* d_in, const int* in_sizes, int n_in,
                              void* d_out, int out_size) {
    const float* pos   = (const float*)d_in[0];
    const int*   ei    = (const int*)  d_in[1];
    const int*   batch = (const int*)  d_in[2];
    const float* W1    = (const float*)d_in[3];
    const float* b1    = (const float*)d_in[4];
    const float* W2    = (const float*)d_in[5];
    const float* b2    = (const float*)d_in[6];
    const float* Wc    = (const float*)d_in[7];
    const float* bc    = (const float*)d_in[8];
    float* out = (float*)d_out;

    int n = in_sizes[0] / 3;
    int e = in_sizes[1] / 2;
    int G = out_size / 2;

    k_init<<<(n + 255) / 256, 256>>>(n, G * 64);
    k_hist<<<(e + 255) / 256, 256>>>(ei, e);
    k_alloc<<<(n + 255) / 256, 256>>>(n);
    k_fill<<<(e + 255) / 256, 256>>>(ei, e);
    k_layer1<<<(n + 7) / 8, 256>>>(pos, W1, b1, n);
    k_layer2<<<(n + 7) / 8, 256>>>(W2, b2, n);
    dim3 pb(64, 4);
    k_pool<<<(n + 511) / 512, pb>>>(batch, n);
    k_cls<<<1, 512>>>(Wc, bc, out, G);
}

// round 3
// speedup vs baseline: 1.1241x; 1.1241x over previous
#include <cuda_runtime.h>

#define NMAX 100000
#define EMAX 3200000
#define GMAX 256
#define FULL 0xFFFFFFFFu

// ---- device scratch (static, no runtime allocation) ----
__device__ int    g_cnt_row[NMAX];
__device__ int    g_cnt_col[NMAX];
__device__ int    g_start[NMAX];
__device__ int    g_cursor[NMAX];
__device__ int    g_gcursor;
__device__ float  g_dis[NMAX];
__device__ float4 g_pos4[NMAX];        // dis[v] * pos[v], padded
__device__ int    g_src[EMAX];
__device__ float  g_h1[NMAX * 32];     // dis[v] * relu(layer1)
__device__ float  g_h2[NMAX * 64];
__device__ float  g_pooled[GMAX * 64];

// ---------------------------------------------------------------------------
// K0: zero counters + pooled
__global__ void k_init(int n, int g64) {
    int i = blockIdx.x * blockDim.x + threadIdx.x;
    if (i < n) { g_cnt_row[i] = 0; g_cnt_col[i] = 0; g_cursor[i] = 0; }
    if (i < g64) g_pooled[i] = 0.0f;
    if (i == 0) g_gcursor = 0;
}

// K1: degree histograms, int4-vectorized edge reads
__global__ void k_hist(const int* __restrict__ ei, int e) {
    int i4 = blockIdx.x * blockDim.x + threadIdx.x;
    int base = i4 * 4;
    if (base + 3 < e) {
        int4 r = *(const int4*)(ei + base);
        int4 c = *(const int4*)(ei + e + base);
        atomicAdd(&g_cnt_row[r.x], 1); atomicAdd(&g_cnt_row[r.y], 1);
        atomicAdd(&g_cnt_row[r.z], 1); atomicAdd(&g_cnt_row[r.w], 1);
        atomicAdd(&g_cnt_col[c.x], 1); atomicAdd(&g_cnt_col[c.y], 1);
        atomicAdd(&g_cnt_col[c.z], 1); atomicAdd(&g_cnt_col[c.w], 1);
    } else {
        for (int i = base; i < e; i++) {
            atomicAdd(&g_cnt_row[ei[i]], 1);
            atomicAdd(&g_cnt_col[ei[e + i]], 1);
        }
    }
}

// K2: dis = rsqrt(deg_row + 1); CSR ranges via warp-aggregated cursor;
//     also writes pre-scaled padded pos4 = dis * pos
__global__ void k_alloc(const float* __restrict__ pos, int n) {
    int i = blockIdx.x * blockDim.x + threadIdx.x;
    int lane = threadIdx.x & 31;
    bool valid = (i < n);
    int c = valid ? g_cnt_col[i] : 0;
    int inc = c;
    #pragma unroll
    for (int o = 1; o < 32; o <<= 1) {
        int t = __shfl_up_sync(FULL, inc, o);
        if (lane >= o) inc += t;
    }
    int ex = inc - c;
    int tot = __shfl_sync(FULL, inc, 31);
    int base = 0;
    if (lane == 31) base = atomicAdd(&g_gcursor, tot);
    base = __shfl_sync(FULL, base, 31);
    if (valid) {
        g_start[i] = base + ex;
        float dv = rsqrtf((float)(g_cnt_row[i] + 1));  // +1 self loop; > 0
        g_dis[i] = dv;
        g_pos4[i] = make_float4(dv * pos[i * 3 + 0],
                                dv * pos[i * 3 + 1],
                                dv * pos[i * 3 + 2], 0.f);
    }
}

// K3: scatter edges into per-destination CSR slots (src only — norm folded out)
__global__ void k_fill(const int* __restrict__ ei, int e) {
    int i4 = blockIdx.x * blockDim.x + threadIdx.x;
    int base = i4 * 4;
    if (base + 3 < e) {
        int4 r = *(const int4*)(ei + base);
        int4 c = *(const int4*)(ei + e + base);
        g_src[g_start[c.x] + atomicAdd(&g_cursor[c.x], 1)] = r.x;
        g_src[g_start[c.y] + atomicAdd(&g_cursor[c.y], 1)] = r.y;
        g_src[g_start[c.z] + atomicAdd(&g_cursor[c.z], 1)] = r.z;
        g_src[g_start[c.w] + atomicAdd(&g_cursor[c.w], 1)] = r.w;
    } else {
        for (int i = base; i < e; i++) {
            int r = ei[i], c = ei[e + i];
            g_src[g_start[c] + atomicAdd(&g_cursor[c], 1)] = r;
        }
    }
}

// K4: layer 1 — aggregate pre-scaled pos4, 3->32 GEMV, store dis*relu
__global__ void k_layer1(const float* __restrict__ W1,
                         const float* __restrict__ b1, int n) {
    __shared__ float sW1[96];
    __shared__ float sb1[32];
    int tid = threadIdx.x;
    if (tid < 96) sW1[tid] = W1[tid];
    if (tid < 32) sb1[tid] = b1[tid];
    __syncthreads();
    int w = tid >> 5, lane = tid & 31;
    int v = blockIdx.x * 8 + w;
    if (v >= n) return;
    int e0 = g_start[v];
    int e1 = e0 + g_cnt_col[v];
    float ax = 0.f, ay = 0.f, az = 0.f;
    for (int j = e0 + lane; j < e1; j += 32) {
        float4 p = g_pos4[g_src[j]];       // 16B aligned gather
        ax += p.x; ay += p.y; az += p.z;
    }
    #pragma unroll
    for (int o = 16; o; o >>= 1) {
        ax += __shfl_xor_sync(FULL, ax, o);
        ay += __shfl_xor_sync(FULL, ay, o);
        az += __shfl_xor_sync(FULL, az, o);
    }
    float dv = g_dis[v];
    float4 ps = g_pos4[v];                 // self loop (already dis-scaled)
    ax = dv * (ax + ps.x);
    ay = dv * (ay + ps.y);
    az = dv * (az + ps.z);
    float o = fmaf(sW1[lane * 3 + 0], ax,
             fmaf(sW1[lane * 3 + 1], ay,
             fmaf(sW1[lane * 3 + 2], az, sb1[lane])));
    g_h1[v * 32 + lane] = dv * fmaxf(o, 0.f);   // pre-scale for layer 2
}

// K5: layer 2 — aggregate h1 (32ch, 128B coalesced gathers), 32->64 GEMV + ReLU
__global__ void k_layer2(const float* __restrict__ W2,
                         const float* __restrict__ b2, int n) {
    __shared__ float sW2T[2048];    // [k][c] transposed
    __shared__ float sb2[64];
    __shared__ float sacc[8][33];
    int tid = threadIdx.x;
    for (int idx = tid; idx < 2048; idx += 256) {
        int c = idx >> 5, k = idx & 31;
        sW2T[k * 64 + c] = W2[idx];   // W2 row-major [64][32]
    }
    if (tid < 64) sb2[tid] = b2[tid];
    __syncthreads();
    int w = tid >> 5, lane = tid & 31;
    int v = blockIdx.x * 8 + w;
    if (v >= n) return;
    int e0 = g_start[v];
    int e1 = e0 + g_cnt_col[v];
    float acc = 0.f;
    for (int base = e0; base < e1; base += 32) {
        int j = base + lane;
        int s = 0;
        if (j < e1) s = g_src[j];
        int m = e1 - base; if (m > 32) m = 32;
        for (int t = 0; t < m; t++) {
            int sv = __shfl_sync(FULL, s, t);
            acc += g_h1[sv * 32 + lane];       // 128B coalesced gather
        }
    }
    acc += g_h1[v * 32 + lane];                // self loop (pre-scaled)
    acc *= g_dis[v];
    sacc[w][lane] = acc;
    __syncwarp();
    float oa = sb2[lane], ob = sb2[lane + 32];
    #pragma unroll
    for (int k = 0; k < 32; k++) {
        float a = sacc[w][k];
        oa = fmaf(a, sW2T[k * 64 + lane], oa);
        ob = fmaf(a, sW2T[k * 64 + lane + 32], ob);
    }
    g_h2[v * 64 + lane]      = fmaxf(oa, 0.f);
    g_h2[v * 64 + lane + 32] = fmaxf(ob, 0.f);
}

// K6: segment max pooling (batch sorted => run-local max, few atomics)
__global__ void k_pool(const int* __restrict__ batch, int n) {
    int c = threadIdx.x;                 // channel 0..63
    int r = threadIdx.y;                 // 0..3
    int v0 = (blockIdx.x * 4 + r) * 128;
    if (v0 >= n) return;
    int v1 = v0 + 128; if (v1 > n) v1 = n;
    int g = batch[v0];
    float m = 0.f;                       // ReLU outputs >= 0
    for (int v = v0; v < v1; v++) {
        int gb = batch[v];
        if (gb != g) {
            atomicMax((int*)&g_pooled[g * 64 + c], __float_as_int(m));
            g = gb; m = 0.f;
        }
        m = fmaxf(m, g_h2[v * 64 + c]);
    }
    atomicMax((int*)&g_pooled[g * 64 + c], __float_as_int(m));
}

// K7: classifier head [G,64] @ Wc^T + bc -> [G,2]
__global__ void k_cls(const float* __restrict__ Wc,
                      const float* __restrict__ bc,
                      float* __restrict__ out, int G) {
    __shared__ float sWc[128];
    __shared__ float sbc[2];
    int t = threadIdx.x;
    if (t < 128) sWc[t] = Wc[t];
    if (t < 2) sbc[t] = bc[t];
    __syncthreads();
    if (t >= G * 2) return;
    int g = t >> 1, k = t & 1;
    float s = sbc[k];
    const float* p = &g_pooled[g * 64];
    #pragma unroll
    for (int c = 0; c < 64; c++)
        s = fmaf(p[c], sWc[k * 64 + c], s);
    out[t] = s;
}

// ---------------------------------------------------------------------------
extern "C" void kernel_launch(void* const* d_in, const int* in_sizes, int n_in,
                              void* d_out, int out_size) {
    const float* pos   = (const float*)d_in[0];
    const int*   ei    = (const int*)  d_in[1];
    const int*   batch = (const int*)  d_in[2];
    const float* W1    = (const float*)d_in[3];
    const float* b1    = (const float*)d_in[4];
    const float* W2    = (const float*)d_in[5];
    const float* b2    = (const float*)d_in[6];
    const float* Wc    = (const float*)d_in[7];
    const float* bc    = (const float*)d_in[8];
    float* out = (float*)d_out;

    int n = in_sizes[0] / 3;
    int e = in_sizes[1] / 2;
    int G = out_size / 2;
    int e4 = (e + 3) / 4;

    k_init<<<(n + 255) / 256, 256>>>(n, G * 64);
    k_hist<<<(e4 + 255) / 256, 256>>>(ei, e);
    k_alloc<<<(n + 255) / 256, 256>>>(pos, n);
    k_fill<<<(e4 + 255) / 256, 256>>>(ei, e);
    k_layer1<<<(n + 7) / 8, 256>>>(W1, b1, n);
    k_layer2<<<(n + 7) / 8, 256>>>(W2, b2, n);
    dim3 pb(64, 4);
    k_pool<<<(n + 511) / 512, pb>>>(batch, n);
    k_cls<<<1, 512>>>(Wc, bc, out, G);
}

// round 4
// speedup vs baseline: 1.1378x; 1.0122x over previous
#include <cuda_runtime.h>

#define NMAX 100000
#define EMAX 3200000
#define GMAX 256
#define FULL 0xFFFFFFFFu

// ---- device scratch (static, no runtime allocation) ----
__device__ int    g_cnt_row[NMAX];
__device__ int    g_cnt_col[NMAX];
__device__ int    g_start[NMAX];
__device__ int    g_cursor[NMAX];      // initialized to g_start in k_alloc
__device__ int    g_gcursor;
__device__ float  g_dis[NMAX];
__device__ float4 g_pos4[NMAX];        // dis[v] * pos[v], padded
__device__ int    g_src[EMAX];
__device__ float  g_h1[NMAX * 32];     // dis[v] * relu(layer1)
__device__ float  g_h2[NMAX * 64];
__device__ float  g_pooled[GMAX * 64];

// ---------------------------------------------------------------------------
// K0: zero counters + pooled
__global__ void k_init(int n, int g64) {
    int i = blockIdx.x * blockDim.x + threadIdx.x;
    if (i < n) { g_cnt_row[i] = 0; g_cnt_col[i] = 0; }
    if (i < g64) g_pooled[i] = 0.0f;
    if (i == 0) g_gcursor = 0;
}

// K1: degree histograms, int4-vectorized edge reads
__global__ void k_hist(const int* __restrict__ ei, int e) {
    int i4 = blockIdx.x * blockDim.x + threadIdx.x;
    int base = i4 * 4;
    if (base + 3 < e) {
        int4 r = *(const int4*)(ei + base);
        int4 c = *(const int4*)(ei + e + base);
        atomicAdd(&g_cnt_row[r.x], 1); atomicAdd(&g_cnt_row[r.y], 1);
        atomicAdd(&g_cnt_row[r.z], 1); atomicAdd(&g_cnt_row[r.w], 1);
        atomicAdd(&g_cnt_col[c.x], 1); atomicAdd(&g_cnt_col[c.y], 1);
        atomicAdd(&g_cnt_col[c.z], 1); atomicAdd(&g_cnt_col[c.w], 1);
    } else {
        for (int i = base; i < e; i++) {
            atomicAdd(&g_cnt_row[ei[i]], 1);
            atomicAdd(&g_cnt_col[ei[e + i]], 1);
        }
    }
}

// K2: dis = rsqrt(deg_row + 1); CSR ranges via warp-aggregated cursor;
//     cursor pre-seeded with start; writes pre-scaled padded pos4 = dis*pos
__global__ void k_alloc(const float* __restrict__ pos, int n) {
    int i = blockIdx.x * blockDim.x + threadIdx.x;
    int lane = threadIdx.x & 31;
    bool valid = (i < n);
    int c = valid ? g_cnt_col[i] : 0;
    int inc = c;
    #pragma unroll
    for (int o = 1; o < 32; o <<= 1) {
        int t = __shfl_up_sync(FULL, inc, o);
        if (lane >= o) inc += t;
    }
    int ex = inc - c;
    int tot = __shfl_sync(FULL, inc, 31);
    int base = 0;
    if (lane == 31) base = atomicAdd(&g_gcursor, tot);
    base = __shfl_sync(FULL, base, 31);
    if (valid) {
        int st = base + ex;
        g_start[i] = st;
        g_cursor[i] = st;                              // fill uses cursor directly
        float dv = rsqrtf((float)(g_cnt_row[i] + 1));  // +1 self loop; > 0
        g_dis[i] = dv;
        g_pos4[i] = make_float4(dv * pos[i * 3 + 0],
                                dv * pos[i * 3 + 1],
                                dv * pos[i * 3 + 2], 0.f);
    }
}

// K3: scatter edges into per-destination CSR slots (cursor holds absolute slot)
__global__ void k_fill(const int* __restrict__ ei, int e) {
    int i4 = blockIdx.x * blockDim.x + threadIdx.x;
    int base = i4 * 4;
    if (base + 3 < e) {
        int4 r = *(const int4*)(ei + base);
        int4 c = *(const int4*)(ei + e + base);
        g_src[atomicAdd(&g_cursor[c.x], 1)] = r.x;
        g_src[atomicAdd(&g_cursor[c.y], 1)] = r.y;
        g_src[atomicAdd(&g_cursor[c.z], 1)] = r.z;
        g_src[atomicAdd(&g_cursor[c.w], 1)] = r.w;
    } else {
        for (int i = base; i < e; i++) {
            int r = ei[i], c = ei[e + i];
            g_src[atomicAdd(&g_cursor[c], 1)] = r;
        }
    }
}

// K4: layer 1 — aggregate pre-scaled pos4, 3->32 GEMV, store dis*relu
__global__ void k_layer1(const float* __restrict__ W1,
                         const float* __restrict__ b1, int n) {
    __shared__ float sW1[96];
    __shared__ float sb1[32];
    int tid = threadIdx.x;
    if (tid < 96) sW1[tid] = W1[tid];
    if (tid < 32) sb1[tid] = b1[tid];
    __syncthreads();
    int w = tid >> 5, lane = tid & 31;
    int v = blockIdx.x * 8 + w;
    if (v >= n) return;
    int e0 = g_start[v];
    int e1 = e0 + g_cnt_col[v];
    float ax = 0.f, ay = 0.f, az = 0.f;
    for (int j = e0 + lane; j < e1; j += 32) {
        float4 p = g_pos4[g_src[j]];       // 16B aligned gather
        ax += p.x; ay += p.y; az += p.z;
    }
    #pragma unroll
    for (int o = 16; o; o >>= 1) {
        ax += __shfl_xor_sync(FULL, ax, o);
        ay += __shfl_xor_sync(FULL, ay, o);
        az += __shfl_xor_sync(FULL, az, o);
    }
    float dv = g_dis[v];
    float4 ps = g_pos4[v];                 // self loop (already dis-scaled)
    ax = dv * (ax + ps.x);
    ay = dv * (ay + ps.y);
    az = dv * (az + ps.z);
    float o = fmaf(sW1[lane * 3 + 0], ax,
             fmaf(sW1[lane * 3 + 1], ay,
             fmaf(sW1[lane * 3 + 2], az, sb1[lane])));
    g_h1[v * 32 + lane] = dv * fmaxf(o, 0.f);   // pre-scale for layer 2
}

// K5: layer 2 — warp = 1 node; lanes = 4 edge-slots x 8 float4 channel groups.
//     4 independent 128B edge gathers in flight per warp; no shfl in inner loop.
__global__ void k_layer2(const float* __restrict__ W2,
                         const float* __restrict__ b2, int n) {
    __shared__ float sW2T[2048];    // [k][c] transposed
    __shared__ float sb2[64];
    __shared__ float sacc[8][32];   // [warp][32 channels], rows 128B aligned
    int tid = threadIdx.x;
    for (int idx = tid; idx < 2048; idx += 256) {
        int c = idx >> 5, k = idx & 31;
        sW2T[k * 64 + c] = W2[idx];   // W2 row-major [64][32]
    }
    if (tid < 64) sb2[tid] = b2[tid];
    __syncthreads();
    int w = tid >> 5, lane = tid & 31;
    int esub = lane >> 3;            // 0..3  edge slot
    int cg   = lane & 7;             // 0..7  float4 channel group
    int v = blockIdx.x * 8 + w;
    if (v >= n) return;
    int e0 = g_start[v];
    int e1 = e0 + g_cnt_col[v];
    float4 acc = make_float4(0.f, 0.f, 0.f, 0.f);
    const float4* __restrict__ h1v = (const float4*)g_h1;
    for (int j = e0 + esub; j < e1; j += 4) {
        int s = __ldg(&g_src[j]);              // 8-lane broadcast, 1 sector
        float4 hv = h1v[s * 8 + cg];           // coalesced 128B per edge
        acc.x += hv.x; acc.y += hv.y; acc.z += hv.z; acc.w += hv.w;
    }
    // reduce across the 4 edge slots (xor 8, 16)
    #pragma unroll
    for (int o = 8; o <= 16; o <<= 1) {
        acc.x += __shfl_xor_sync(FULL, acc.x, o);
        acc.y += __shfl_xor_sync(FULL, acc.y, o);
        acc.z += __shfl_xor_sync(FULL, acc.z, o);
        acc.w += __shfl_xor_sync(FULL, acc.w, o);
    }
    float dv = g_dis[v];
    if (esub == 0) {                           // lanes 0..7 commit 4 channels each
        float4 sl = h1v[v * 8 + cg];           // self loop (pre-scaled)
        acc.x = (acc.x + sl.x) * dv;
        acc.y = (acc.y + sl.y) * dv;
        acc.z = (acc.z + sl.z) * dv;
        acc.w = (acc.w + sl.w) * dv;
        ((float4*)sacc[w])[cg] = acc;
    }
    __syncwarp();
    float oa = sb2[lane], ob = sb2[lane + 32];
    #pragma unroll
    for (int k = 0; k < 32; k++) {
        float a = sacc[w][k];                  // broadcast
        oa = fmaf(a, sW2T[k * 64 + lane], oa);
        ob = fmaf(a, sW2T[k * 64 + lane + 32], ob);
    }
    g_h2[v * 64 + lane]      = fmaxf(oa, 0.f);
    g_h2[v * 64 + lane + 32] = fmaxf(ob, 0.f);
}

// K6: segment max pooling (batch sorted => run-local max, few atomics)
__global__ void k_pool(const int* __restrict__ batch, int n) {
    int c = threadIdx.x;                 // channel 0..63
    int r = threadIdx.y;                 // 0..3
    int v0 = (blockIdx.x * 4 + r) * 128;
    if (v0 >= n) return;
    int v1 = v0 + 128; if (v1 > n) v1 = n;
    int g = batch[v0];
    float m = 0.f;                       // ReLU outputs >= 0
    for (int v = v0; v < v1; v++) {
        int gb = batch[v];
        if (gb != g) {
            atomicMax((int*)&g_pooled[g * 64 + c], __float_as_int(m));
            g = gb; m = 0.f;
        }
        m = fmaxf(m, g_h2[v * 64 + c]);
    }
    atomicMax((int*)&g_pooled[g * 64 + c], __float_as_int(m));
}

// K7: classifier head [G,64] @ Wc^T + bc -> [G,2]
__global__ void k_cls(const float* __restrict__ Wc,
                      const float* __restrict__ bc,
                      float* __restrict__ out, int G) {
    __shared__ float sWc[128];
    __shared__ float sbc[2];
    int t = threadIdx.x;
    if (t < 128) sWc[t] = Wc[t];
    if (t < 2) sbc[t] = bc[t];
    __syncthreads();
    if (t >= G * 2) return;
    int g = t >> 1, k = t & 1;
    float s = sbc[k];
    const float* p = &g_pooled[g * 64];
    #pragma unroll
    for (int c = 0; c < 64; c++)
        s = fmaf(p[c], sWc[k * 64 + c], s);
    out[t] = s;
}

// ---------------------------------------------------------------------------
extern "C" void kernel_launch(void* const* d_in, const int* in_sizes, int n_in,
                              void* d_out, int out_size) {
    const float* pos   = (const float*)d_in[0];
    const int*   ei    = (const int*)  d_in[1];
    const int*   batch = (const int*)  d_in[2];
    const float* W1    = (const float*)d_in[3];
    const float* b1    = (const float*)d_in[4];
    const float* W2    = (const float*)d_in[5];
    const float* b2    = (const float*)d_in[6];
    const float* Wc    = (const float*)d_in[7];
    const float* bc    = (const float*)d_in[8];
    float* out = (float*)d_out;

    int n = in_sizes[0] / 3;
    int e = in_sizes[1] / 2;
    int G = out_size / 2;
    int e4 = (e + 3) / 4;

    k_init<<<(n + 255) / 256, 256>>>(n, G * 64);
    k_hist<<<(e4 + 255) / 256, 256>>>(ei, e);
    k_alloc<<<(n + 255) / 256, 256>>>(pos, n);
    k_fill<<<(e4 + 255) / 256, 256>>>(ei, e);
    k_layer1<<<(n + 7) / 8, 256>>>(W1, b1, n);
    k_layer2<<<(n + 7) / 8, 256>>>(W2, b2, n);
    dim3 pb(64, 4);
    k_pool<<<(n + 511) / 512, pb>>>(batch, n);
    k_cls<<<1, 512>>>(Wc, bc, out, G);
}